// round 16
// baseline (speedup 1.0000x reference)
#include <cuda_runtime.h>
#include <cuda_bf16.h>
#include <cstdint>

#define N_NODES 50000
#define N_EDGES 800000
#define F_INPUT 256
#define HID     64
#define NHEADS  4
#define NG      64
#define NB_SCAN 196   // ceil(50000/256)

// ---------------- scratch (device globals: no allocation allowed) ----------------
__device__ int   g_deg[N_NODES];          // zero-init at load; self-cleared each run
__device__ float g_dinv[N_NODES];
__device__ int   g_rowptr[N_NODES + 1];
__device__ int   g_epos[N_EDGES];         // per-edge sequence number within its dst
__device__ int   g_csrsrc[N_EDGES];
__device__ int   g_bsum[256];
__device__ __nv_bfloat162 g_t2[N_NODES * 32];         // GEMM out (64 ch as bf16 pairs)
__device__ float g_h [N_NODES * HID];                 // layer activations (fp32)
__device__ __nv_bfloat162 g_hh2[N_NODES * 128];       // h @ Wg, bf16 pairs (256 ch)
__device__ float g_as[N_NODES * NHEADS];              // attention src logits
__device__ float g_ad[N_NODES * NHEADS];              // attention dst logits
__device__ float4 g_si4 [N_NODES];                    // per-dst 1/sum (4 heads)
__device__ __nv_bfloat162 g_alf[N_EDGES * 2];         // per-edge unnorm alpha (4 heads bf16)
__device__ __nv_bfloat162 g_gat2[N_NODES * 128];      // GAT output (bf16 pairs)
__device__ float g_pool[NG * NHEADS * HID];
__device__ int   g_gstart[NG + 1];
__device__ float g_Ms[HID * NHEADS];                  // Wg folded with att_src
__device__ float g_Md[HID * NHEADS];                  // Wg folded with att_dst

__device__ __forceinline__ float lrelu(float x) { return x > 0.f ? x : 0.2f * x; }

// ---------------- CSR construction ----------------
// hist: 8 edges/thread (MLP-8 vs 318-cyc ATOMG); records per-edge sequence number
__global__ void k_hist(const int* __restrict__ ei) {
    int t = blockIdx.x * blockDim.x + threadIdx.x;
    int e = t * 8;
    if (e < N_EDGES) {
        int4 d0 = *(const int4*)&ei[N_EDGES + e];
        int4 d1 = *(const int4*)&ei[N_EDGES + e + 4];
        int4 p0, p1;
        p0.x = atomicAdd(&g_deg[d0.x], 1);
        p0.y = atomicAdd(&g_deg[d0.y], 1);
        p0.z = atomicAdd(&g_deg[d0.z], 1);
        p0.w = atomicAdd(&g_deg[d0.w], 1);
        p1.x = atomicAdd(&g_deg[d1.x], 1);
        p1.y = atomicAdd(&g_deg[d1.y], 1);
        p1.z = atomicAdd(&g_deg[d1.z], 1);
        p1.w = atomicAdd(&g_deg[d1.w], 1);
        *(int4*)&g_epos[e]     = p0;
        *(int4*)&g_epos[e + 4] = p1;
    }
}

// block-local exclusive scan of degrees; zeroes g_deg for the next replay
__global__ void k_scan_local() {
    __shared__ int sm[256];
    int t = threadIdx.x;
    int i = blockIdx.x * 256 + t;
    int d = (i < N_NODES) ? g_deg[i] : 0;
    if (i < N_NODES) g_deg[i] = 0;        // self-clear (replaces front-of-chain memset)
    sm[t] = d;
    __syncthreads();
    for (int off = 1; off < 256; off <<= 1) {
        int u = (t >= off) ? sm[t - off] : 0;
        __syncthreads();
        sm[t] += u;
        __syncthreads();
    }
    int incl = sm[t];
    if (i < N_NODES) {
        g_rowptr[i] = incl - d;           // local exclusive prefix (fixed up later)
        g_dinv[i]   = rsqrtf((float)(d + 1));
    }
    if (t == 255) g_bsum[blockIdx.x] = incl;
}

// merged: every block redundantly scans the 196 block sums, then fixes up its slice
__global__ void k_fixup() {
    __shared__ int sm[256];
    int t = threadIdx.x;
    sm[t] = (t < NB_SCAN) ? g_bsum[t] : 0;
    __syncthreads();
    for (int off = 1; off < 256; off <<= 1) {
        int u = (t >= off) ? sm[t - off] : 0;
        __syncthreads();
        sm[t] += u;
        __syncthreads();
    }
    int boff = (blockIdx.x > 0) ? sm[blockIdx.x - 1] : 0;
    int i = blockIdx.x * 256 + t;
    if (i < N_NODES)
        g_rowptr[i] = g_rowptr[i] + boff;
    if (i == 0) g_rowptr[N_NODES] = N_EDGES;
}

// atomic-free scatter: slot = rowptr[dst] + saved sequence number
__global__ void k_scatter(const int* __restrict__ ei) {
    int t = blockIdx.x * blockDim.x + threadIdx.x;
    int e = t * 4;
    if (e < N_EDGES) {
        int4 s = *(const int4*)&ei[e];
        int4 d = *(const int4*)&ei[N_EDGES + e];
        int4 p = *(const int4*)&g_epos[e];
        g_csrsrc[g_rowptr[d.x] + p.x] = s.x;
        g_csrsrc[g_rowptr[d.y] + p.y] = s.y;
        g_csrsrc[g_rowptr[d.z] + p.z] = s.z;
        g_csrsrc[g_rowptr[d.w] + p.w] = s.w;
    }
}

// fold Wg with attention vectors: Ms[k,h] = sum_c Wg[k, h*64+c] * att_src[h,c]
__global__ void k_fold(const float* __restrict__ Wg, const float* __restrict__ att_src,
                       const float* __restrict__ att_dst) {
    int t = threadIdx.x;          // 256 threads: k = t>>2, h = t&3
    int k = t >> 2, h = t & 3;
    float s = 0.f, d = 0.f;
    for (int c = 0; c < 64; c++) {
        float w = Wg[k * 256 + h * 64 + c];
        s += w * att_src[h * 64 + c];
        d += w * att_dst[h * 64 + c];
    }
    g_Ms[k * 4 + h] = s;
    g_Md[k * 4 + h] = d;
}

// ---------------- tensor-core GEMM (HMMA bf16, fp32 accum) ----------------------
#define APAD 40   // bf16 per A smem row (32 used)
#define BPAD 72   // bf16 per B smem row (64 used)

__device__ __forceinline__ void ldsm_x4(unsigned* r, unsigned addr) {
    asm volatile("ldmatrix.sync.aligned.m8n8.x4.shared.b16 {%0,%1,%2,%3}, [%4];"
                 : "=r"(r[0]), "=r"(r[1]), "=r"(r[2]), "=r"(r[3]) : "r"(addr));
}
__device__ __forceinline__ void ldsm_x4_t(unsigned* r, unsigned addr) {
    asm volatile("ldmatrix.sync.aligned.m8n8.x4.trans.shared.b16 {%0,%1,%2,%3}, [%4];"
                 : "=r"(r[0]), "=r"(r[1]), "=r"(r[2]), "=r"(r[3]) : "r"(addr));
}
__device__ __forceinline__ void mma_bf16(float* c, const unsigned* a,
                                         unsigned b0, unsigned b1) {
    asm volatile(
        "mma.sync.aligned.m16n8k16.row.col.f32.bf16.bf16.f32 "
        "{%0,%1,%2,%3}, {%4,%5,%6,%7}, {%8,%9}, {%0,%1,%2,%3};"
        : "+f"(c[0]), "+f"(c[1]), "+f"(c[2]), "+f"(c[3])
        : "r"(a[0]), "r"(a[1]), "r"(a[2]), "r"(a[3]), "r"(b0), "r"(b1));
}

__global__ __launch_bounds__(256) void k_gemm(const float* __restrict__ Aext,
                                              const float* __restrict__ W,
                                              int K, int nCols, int mode) {
    const float* __restrict__ A = (mode == 0) ? Aext : g_h;

    __shared__ __nv_bfloat16 As[128 * APAD];
    __shared__ __nv_bfloat16 Bs[32 * BPAD];

    int tid  = threadIdx.x;
    int lane = tid & 31, warp = tid >> 5;
    int wr = warp >> 1, wc = warp & 1;         // 4 x 2 warp grid
    int m0 = blockIdx.x * 128;
    int colb = blockIdx.y * 64;

    unsigned As_base = (unsigned)__cvta_generic_to_shared(As);
    unsigned Bs_base = (unsigned)__cvta_generic_to_shared(Bs);

    float c[2][4][4] = {};

    for (int k0 = 0; k0 < K; k0 += 32) {
#pragma unroll
        for (int i = 0; i < 4; i++) {
            int li  = i * 256 + tid;
            int row = li >> 3, seg = li & 7;
            float4 av = make_float4(0.f, 0.f, 0.f, 0.f);
            int grow = m0 + row;
            if (grow < N_NODES)
                av = *(const float4*)&A[(long)grow * K + k0 + seg * 4];
            __nv_bfloat162 p0 = __floats2bfloat162_rn(av.x, av.y);
            __nv_bfloat162 p1 = __floats2bfloat162_rn(av.z, av.w);
            *(__nv_bfloat162*)&As[row * APAD + seg * 4]     = p0;
            *(__nv_bfloat162*)&As[row * APAD + seg * 4 + 2] = p1;
        }
#pragma unroll
        for (int i = 0; i < 2; i++) {
            int li  = i * 256 + tid;
            int row = li >> 4, seg = li & 15;
            float4 wv = *(const float4*)&W[(long)(k0 + row) * nCols + colb + seg * 4];
            __nv_bfloat162 p0 = __floats2bfloat162_rn(wv.x, wv.y);
            __nv_bfloat162 p1 = __floats2bfloat162_rn(wv.z, wv.w);
            *(__nv_bfloat162*)&Bs[row * BPAD + seg * 4]     = p0;
            *(__nv_bfloat162*)&Bs[row * BPAD + seg * 4 + 2] = p1;
        }
        __syncthreads();

#pragma unroll
        for (int kk = 0; kk < 2; kk++) {
            int k16 = kk * 16;
            unsigned a[2][4], b[2][4];
            int arow = wr * 32 + (lane & 15);
            int acol = k16 + (lane >> 4) * 8;
#pragma unroll
            for (int mi = 0; mi < 2; mi++)
                ldsm_x4(a[mi], As_base + ((arow + mi * 16) * APAD + acol) * 2);
            int brow = k16 + (lane & 15);
#pragma unroll
            for (int ni = 0; ni < 2; ni++) {
                int bcol = wc * 32 + ni * 16 + (lane >> 4) * 8;
                ldsm_x4_t(b[ni], Bs_base + (brow * BPAD + bcol) * 2);
            }
#pragma unroll
            for (int mi = 0; mi < 2; mi++)
#pragma unroll
                for (int j = 0; j < 4; j++)
                    mma_bf16(c[mi][j], a[mi], b[j >> 1][(j & 1) * 2],
                             b[j >> 1][(j & 1) * 2 + 1]);
        }
        __syncthreads();
    }

    __nv_bfloat162* outp = (mode == 2) ? g_hh2 : g_t2;
    int ostride = (mode == 2) ? 128 : 32;
    int obase   = (mode == 2) ? (colb >> 1) : 0;
    int trow = lane >> 2, tq = lane & 3;
#pragma unroll
    for (int mi = 0; mi < 2; mi++) {
#pragma unroll
        for (int j = 0; j < 4; j++) {
            int row  = m0 + wr * 32 + mi * 16 + trow;
            int cidx = obase + wc * 16 + j * 4 + tq;
            if (row < N_NODES)
                outp[row * ostride + cidx] = __floats2bfloat162_rn(c[mi][j][0], c[mi][j][1]);
            if (row + 8 < N_NODES)
                outp[(row + 8) * ostride + cidx] = __floats2bfloat162_rn(c[mi][j][2], c[mi][j][3]);
        }
    }
}

// ---------------- GCN aggregation (serial shfl-broadcast form) ----------------
__global__ void k_gcn(const float* __restrict__ bias) {
    int warp = (blockIdx.x * blockDim.x + threadIdx.x) >> 5;
    int lane = threadIdx.x & 31;
    if (warp >= N_NODES) return;
    int dst = warp;
    int r0 = g_rowptr[dst], r1 = g_rowptr[dst + 1];
    float wd = g_dinv[dst];
    const __nv_bfloat162* __restrict__ t2 = g_t2;
    float2 f = __bfloat1622float2(t2[dst * 32 + lane]);   // self-loop
    float acc0 = f.x * wd;
    float acc1 = f.y * wd;
    for (int e0 = r0; e0 < r1; e0 += 32) {
        int idx = e0 + lane;
        int s = 0; float w = 0.f;
        if (idx < r1) { s = g_csrsrc[idx]; w = g_dinv[s]; }
        int cnt = min(32, r1 - e0);
        for (int j = 0; j < cnt; j++) {
            int   ss = __shfl_sync(0xffffffffu, s, j);
            float ww = __shfl_sync(0xffffffffu, w, j);
            float2 v = __bfloat1622float2(t2[ss * 32 + lane]);
            acc0 += v.x * ww;
            acc1 += v.y * ww;
        }
    }
    float2 b = *(const float2*)&bias[2 * lane];
    float2 o;
    o.x = fmaxf(acc0 * wd + b.x, 0.f);
    o.y = fmaxf(acc1 * wd + b.y, 0.f);
    *(float2*)&g_h[dst * 64 + 2 * lane] = o;
}

// ---------------- attention logits from fp32 h via folded matrices ----------------
__global__ void k_att2() {
    int warp = (blockIdx.x * blockDim.x + threadIdx.x) >> 5;
    int lane = threadIdx.x & 31;
    if (warp >= N_NODES) return;
    int n = warp;
    int head = lane >> 3;
    int q    = lane & 7;
    float4 h1 = *(const float4*)&g_h[n * 64 + q * 8];
    float4 h2 = *(const float4*)&g_h[n * 64 + q * 8 + 4];
    float hv[8] = {h1.x, h1.y, h1.z, h1.w, h2.x, h2.y, h2.z, h2.w};
    float ps = 0.f, pd = 0.f;
#pragma unroll
    for (int i = 0; i < 8; i++) {
        int k = q * 8 + i;
        ps += hv[i] * g_Ms[k * 4 + head];
        pd += hv[i] * g_Md[k * 4 + head];
    }
#pragma unroll
    for (int off = 1; off < 8; off <<= 1) {
        ps += __shfl_xor_sync(0xffffffffu, ps, off);
        pd += __shfl_xor_sync(0xffffffffu, pd, off);
    }
    if (q == 0) {
        g_as[n * 4 + head] = ps;
        g_ad[n * 4 + head] = pd;
    }
}

__device__ __forceinline__ float pick4(float x, float y, float z, float w, int h) {
    return h == 0 ? x : h == 1 ? y : h == 2 ? z : w;
}

// ---------------- GAT phase 1: per-edge alpha + per-dst sums (side stream) -------
// no max-subtraction: logits are O(1..10), exp is safe in fp32; /s normalizes.
__global__ void k_gat1() {
    int warp = (blockIdx.x * blockDim.x + threadIdx.x) >> 5;
    int lane = threadIdx.x & 31;
    if (warp >= N_NODES) return;
    int dst = warp;
    int r0 = g_rowptr[dst], r1 = g_rowptr[dst + 1];
    const float4* as4 = (const float4*)g_as;
    float4 adv = ((const float4*)g_ad)[dst];

    float s0 = 0.f, s1 = 0.f, s2 = 0.f, s3 = 0.f;
    for (int e = r0 + lane; e < r1; e += 32) {
        int src = g_csrsrc[e];
        float4 av = as4[src];
        float a0 = __expf(lrelu(av.x + adv.x));
        float a1 = __expf(lrelu(av.y + adv.y));
        float a2 = __expf(lrelu(av.z + adv.z));
        float a3 = __expf(lrelu(av.w + adv.w));
        s0 += a0; s1 += a1; s2 += a2; s3 += a3;
        float2 pk;
        ((__nv_bfloat162*)&pk)[0] = __floats2bfloat162_rn(a0, a1);
        ((__nv_bfloat162*)&pk)[1] = __floats2bfloat162_rn(a2, a3);
        *(float2*)&g_alf[2 * e] = pk;       // 8B coalesced-ish write
    }
    if (lane == 0) {   // self-loop contributes to the sum
        float4 av = as4[dst];
        s0 += __expf(lrelu(av.x + adv.x));
        s1 += __expf(lrelu(av.y + adv.y));
        s2 += __expf(lrelu(av.z + adv.z));
        s3 += __expf(lrelu(av.w + adv.w));
    }
#pragma unroll
    for (int off = 16; off > 0; off >>= 1) {
        s0 += __shfl_down_sync(0xffffffffu, s0, off);
        s1 += __shfl_down_sync(0xffffffffu, s1, off);
        s2 += __shfl_down_sync(0xffffffffu, s2, off);
        s3 += __shfl_down_sync(0xffffffffu, s3, off);
    }
    if (lane == 0)
        g_si4[dst] = make_float4(1.f / s0, 1.f / s1, 1.f / s2, 1.f / s3);
}

// ---------------- GAT phase 2: serial weighted bf16 gather, alpha from table -----
__global__ void k_gat2() {
    int warp = (blockIdx.x * blockDim.x + threadIdx.x) >> 5;
    int lane = threadIdx.x & 31;
    if (warp >= N_NODES) return;
    int dst = warp;
    int r0 = g_rowptr[dst], r1 = g_rowptr[dst + 1];
    float4 adv = ((const float4*)g_ad)[dst];
    float4 iv  = g_si4[dst];

    int head = lane >> 3;
    float inv = pick4(iv.x, iv.y, iv.z, iv.w, head);
    float adh = pick4(adv.x, adv.y, adv.z, adv.w, head);
    int hp = head >> 1;          // which bf16x2 word holds this head
    int hl = head & 1;           // low/high half

    const float4* hh4 = (const float4*)g_hh2;   // 32 float4 per node row
    float a0 = 0.f, a1 = 0.f, a2 = 0.f, a3 = 0.f, a4 = 0.f, a5 = 0.f, a6 = 0.f, a7 = 0.f;
    {   // self-loop (one exp per dst — cheap)
        float ash = g_as[dst * 4 + head];
        float al  = __expf(lrelu(ash + adh)) * inv;
        float4 raw = hh4[dst * 32 + lane];
        const __nv_bfloat162* bp = (const __nv_bfloat162*)&raw;
        float2 f0 = __bfloat1622float2(bp[0]);
        float2 f1 = __bfloat1622float2(bp[1]);
        float2 f2 = __bfloat1622float2(bp[2]);
        float2 f3 = __bfloat1622float2(bp[3]);
        a0 += f0.x * al; a1 += f0.y * al; a2 += f1.x * al; a3 += f1.y * al;
        a4 += f2.x * al; a5 += f2.y * al; a6 += f3.x * al; a7 += f3.y * al;
    }
    for (int e0 = r0; e0 < r1; e0 += 32) {
        int idx = e0 + lane;
        int sv = (idx < r1) ? g_csrsrc[idx] : 0;
        int cnt = min(32, r1 - e0);
        for (int j = 0; j < cnt; j++) {
            int src = __shfl_sync(0xffffffffu, sv, j);
            // broadcast load of this edge's alpha word for our head pair
            float2 aw = __bfloat1622float2(g_alf[2 * (e0 + j) + hp]);
            float al  = (hl ? aw.y : aw.x) * inv;
            float4 raw = hh4[src * 32 + lane];
            const __nv_bfloat162* bp = (const __nv_bfloat162*)&raw;
            float2 f0 = __bfloat1622float2(bp[0]);
            float2 f1 = __bfloat1622float2(bp[1]);
            float2 f2 = __bfloat1622float2(bp[2]);
            float2 f3 = __bfloat1622float2(bp[3]);
            a0 += f0.x * al; a1 += f0.y * al; a2 += f1.x * al; a3 += f1.y * al;
            a4 += f2.x * al; a5 += f2.y * al; a6 += f3.x * al; a7 += f3.y * al;
        }
    }
    float4 ov;
    __nv_bfloat162* op = (__nv_bfloat162*)&ov;
    op[0] = __floats2bfloat162_rn(a0, a1);
    op[1] = __floats2bfloat162_rn(a2, a3);
    op[2] = __floats2bfloat162_rn(a4, a5);
    op[3] = __floats2bfloat162_rn(a6, a7);
    *(float4*)&g_gat2[dst * 128 + lane * 4] = ov;
}

// ---------------- pooling (batch is sorted) ----------------
__global__ void k_gstart(const int* __restrict__ batch) {
    int n = blockIdx.x * blockDim.x + threadIdx.x;
    if (n >= N_NODES) return;
    int b = batch[n];
    if (n == 0)
        for (int g = 0; g <= b; g++) g_gstart[g] = 0;
    if (n == N_NODES - 1) {
        for (int g = b + 1; g <= NG; g++) g_gstart[g] = N_NODES;
    } else {
        int b2 = batch[n + 1];
        for (int g = b + 1; g <= b2; g++) g_gstart[g] = n + 1;
    }
}

// grid dim3(NG, 4): 32 bf16-pair channels x 8 node-slots per block
__global__ void k_pool(const float* __restrict__ bg) {
    int g = blockIdx.x;
    int pair = blockIdx.y * 32 + (threadIdx.x & 31);   // 0..127
    int slot = threadIdx.x >> 5;                       // 0..7
    int st = g_gstart[g], en = g_gstart[g + 1];
    float ax = 0.f, ay = 0.f;
    for (int n = st + slot; n < en; n += 8) {
        float2 v = __bfloat1622float2(g_gat2[n * 128 + pair]);
        ax += v.x; ay += v.y;
    }
    __shared__ float smx[256], smy[256];
    smx[threadIdx.x] = ax; smy[threadIdx.x] = ay;
    __syncthreads();
    if (slot == 0) {
        int pl = threadIdx.x & 31;
        float tx = 0.f, ty = 0.f;
#pragma unroll
        for (int s = 0; s < 8; s++) { tx += smx[s * 32 + pl]; ty += smy[s * 32 + pl]; }
        int cnt = en - st;
        float vx = 0.f, vy = 0.f;
        if (cnt > 0) {
            float ic = 1.f / (float)cnt;
            vx = tx * ic + bg[pair * 2];
            vy = ty * ic + bg[pair * 2 + 1];
        }
        *(float2*)&g_pool[g * 256 + pair * 2] = make_float2(vx, vy);
    }
}

// ---------------- final MLP ----------------
__global__ void k_mlp(const float* __restrict__ Wf1, const float* __restrict__ bf1,
                      const float* __restrict__ Wf2, const float* __restrict__ bf2,
                      float* __restrict__ out) {
    int g = blockIdx.x;
    int j = threadIdx.x;   // 64 threads
    float acc = bf1[j];
    const float* p = &g_pool[g * 256];
    for (int c = 0; c < 256; c++)
        acc += p[c] * Wf1[c * 64 + j];
    float z = fmaxf(acc, 0.f) * Wf2[j];
#pragma unroll
    for (int off = 16; off > 0; off >>= 1)
        z += __shfl_xor_sync(0xffffffffu, z, off);
    __shared__ float sm[2];
    if ((threadIdx.x & 31) == 0) sm[threadIdx.x >> 5] = z;
    __syncthreads();
    if (threadIdx.x == 0) out[g] = sm[0] + sm[1] + bf2[0];
}

// ---------------- launch ----------------
extern "C" void kernel_launch(void* const* d_in, const int* in_sizes, int n_in,
                              void* d_out, int out_size) {
    const float* x       = (const float*)d_in[0];
    const int*   ei      = (const int*)  d_in[1];
    const int*   batch   = (const int*)  d_in[2];
    const float* W1      = (const float*)d_in[3];
    const float* b1      = (const float*)d_in[4];
    const float* W2      = (const float*)d_in[5];
    const float* b2      = (const float*)d_in[6];
    const float* Wg      = (const float*)d_in[7];
    const float* att_src = (const float*)d_in[8];
    const float* att_dst = (const float*)d_in[9];
    const float* bg      = (const float*)d_in[10];
    const float* Wf1     = (const float*)d_in[11];
    const float* bf1     = (const float*)d_in[12];
    const float* Wf2     = (const float*)d_in[13];
    const float* bf2     = (const float*)d_in[14];
    float* out = (float*)d_out;

    // lazily created side-stream resources (first call is the non-captured
    // correctness run; creation happens there, never during capture)
    static cudaStream_t s1 = nullptr;
    static cudaEvent_t  ev_fork = nullptr, ev_csr = nullptr;
    static cudaEvent_t  ev_h = nullptr, ev_att = nullptr;
    if (!s1) {
        cudaStreamCreateWithFlags(&s1, cudaStreamNonBlocking);
        cudaEventCreateWithFlags(&ev_fork, cudaEventDisableTiming);
        cudaEventCreateWithFlags(&ev_csr,  cudaEventDisableTiming);
        cudaEventCreateWithFlags(&ev_h,    cudaEventDisableTiming);
        cudaEventCreateWithFlags(&ev_att,  cudaEventDisableTiming);
    }

    dim3 gemm_grid1((N_NODES + 127) / 128, 1);
    dim3 gemm_grid4((N_NODES + 127) / 128, 4);
    int  warp_blocks = (N_NODES + 7) / 8;   // 8 warps / 256-thread block

    // fork: CSR chain on side stream, concurrent with GEMM1
    cudaEventRecord(ev_fork, 0);
    cudaStreamWaitEvent(s1, ev_fork, 0);

    k_hist      <<<(N_EDGES / 8 + 255) / 256, 256, 0, s1>>>(ei);
    k_scan_local<<<NB_SCAN, 256, 0, s1>>>();
    k_fixup     <<<NB_SCAN, 256, 0, s1>>>();
    k_scatter   <<<(N_EDGES / 4 + 255) / 256, 256, 0, s1>>>(ei);
    cudaEventRecord(ev_csr, s1);            // join point: only CSR needed by gcn1
    k_gstart    <<<(N_NODES + 255) / 256, 256, 0, s1>>>(batch);
    k_fold      <<<1, 256, 0, s1>>>(Wg, att_src, att_dst);

    // main stream: GEMM1 overlaps the CSR build
    k_gemm<<<gemm_grid1, 256>>>(x, W1, F_INPUT, 64, 0);

    // join: aggregation needs CSR
    cudaStreamWaitEvent(0, ev_csr, 0);

    k_gcn <<<warp_blocks, 256>>>(b1);
    k_gemm<<<gemm_grid1, 256>>>(x, W2, 64, 64, 1);
    k_gcn <<<warp_blocks, 256>>>(b2);

    // fork: attention logits + per-edge alpha (need g_h + CSR, NOT hh2)
    // run on s1 concurrent with GEMM3
    cudaEventRecord(ev_h, 0);
    cudaStreamWaitEvent(s1, ev_h, 0);
    k_att2<<<warp_blocks, 256, 0, s1>>>();
    k_gat1<<<warp_blocks, 256, 0, s1>>>();
    cudaEventRecord(ev_att, s1);

    k_gemm<<<gemm_grid4, 256>>>(x, Wg, 64, 256, 2);
    cudaStreamWaitEvent(0, ev_att, 0);      // also orders gstart/fold before pool

    k_gat2<<<warp_blocks, 256>>>();
    k_pool<<<dim3(NG, 4), 256>>>(bg);
    k_mlp <<<NG, 64>>>(Wf1, bf1, Wf2, bf2, out);
}

// round 17
// speedup vs baseline: 1.1123x; 1.1123x over previous
#include <cuda_runtime.h>
#include <cuda_bf16.h>
#include <cstdint>

#define N_NODES 50000
#define N_EDGES 800000
#define F_INPUT 256
#define HID     64
#define NHEADS  4
#define NG      64
#define NB_SCAN 196   // ceil(50000/256)

// ---------------- scratch (device globals: no allocation allowed) ----------------
__device__ int   g_deg[N_NODES];          // zero-init at load; self-cleared each run
__device__ float g_dinv[N_NODES];
__device__ int   g_rowptr[N_NODES + 1];
__device__ int   g_epos[N_EDGES];         // per-edge sequence number within its dst
__device__ int   g_csrsrc[N_EDGES];
__device__ int   g_bsum[256];
__device__ __nv_bfloat162 g_t2[N_NODES * 32];         // GEMM out (64 ch as bf16 pairs)
__device__ float g_h [N_NODES * HID];                 // layer activations (fp32)
__device__ __nv_bfloat162 g_hh2[N_NODES * 128];       // h @ Wg, bf16 pairs (256 ch)
__device__ float g_as[N_NODES * NHEADS];              // attention src logits
__device__ float g_ad[N_NODES * NHEADS];              // attention dst logits
__device__ float4 g_si4 [N_NODES];                    // per-dst 1/sum (4 heads)
__device__ __nv_bfloat162 g_alf[N_EDGES * 2];         // per-edge unnorm alpha (4 heads bf16)
__device__ __nv_bfloat162 g_gat2[N_NODES * 128];      // GAT output (bf16 pairs)
__device__ float g_pool[NG * NHEADS * HID];
__device__ int   g_gstart[NG + 1];
__device__ float g_Ms[HID * NHEADS];                  // Wg folded with att_src
__device__ float g_Md[HID * NHEADS];                  // Wg folded with att_dst

__device__ __forceinline__ float lrelu(float x) { return x > 0.f ? x : 0.2f * x; }

// ---------------- CSR construction ----------------
// hist: 8 edges/thread (MLP-8 vs 318-cyc ATOMG); records per-edge sequence number
__global__ void k_hist(const int* __restrict__ ei) {
    int t = blockIdx.x * blockDim.x + threadIdx.x;
    int e = t * 8;
    if (e < N_EDGES) {
        int4 d0 = *(const int4*)&ei[N_EDGES + e];
        int4 d1 = *(const int4*)&ei[N_EDGES + e + 4];
        int4 p0, p1;
        p0.x = atomicAdd(&g_deg[d0.x], 1);
        p0.y = atomicAdd(&g_deg[d0.y], 1);
        p0.z = atomicAdd(&g_deg[d0.z], 1);
        p0.w = atomicAdd(&g_deg[d0.w], 1);
        p1.x = atomicAdd(&g_deg[d1.x], 1);
        p1.y = atomicAdd(&g_deg[d1.y], 1);
        p1.z = atomicAdd(&g_deg[d1.z], 1);
        p1.w = atomicAdd(&g_deg[d1.w], 1);
        *(int4*)&g_epos[e]     = p0;
        *(int4*)&g_epos[e + 4] = p1;
    }
}

// block-local exclusive scan of degrees; zeroes g_deg for the next replay.
// extra block NB_SCAN computes the folded attention matrices (covered by ev_csr).
__global__ void k_scan_local(const float* __restrict__ Wg,
                             const float* __restrict__ att_src,
                             const float* __restrict__ att_dst) {
    int t = threadIdx.x;
    if (blockIdx.x == NB_SCAN) {          // fold block
        int k = t >> 2, h = t & 3;
        float s = 0.f, d = 0.f;
        for (int c = 0; c < 64; c++) {
            float w = Wg[k * 256 + h * 64 + c];
            s += w * att_src[h * 64 + c];
            d += w * att_dst[h * 64 + c];
        }
        g_Ms[k * 4 + h] = s;
        g_Md[k * 4 + h] = d;
        return;
    }
    __shared__ int sm[256];
    int i = blockIdx.x * 256 + t;
    int d = (i < N_NODES) ? g_deg[i] : 0;
    if (i < N_NODES) g_deg[i] = 0;        // self-clear (replaces front-of-chain memset)
    sm[t] = d;
    __syncthreads();
    for (int off = 1; off < 256; off <<= 1) {
        int u = (t >= off) ? sm[t - off] : 0;
        __syncthreads();
        sm[t] += u;
        __syncthreads();
    }
    int incl = sm[t];
    if (i < N_NODES) {
        g_rowptr[i] = incl - d;           // local exclusive prefix (fixed up later)
        g_dinv[i]   = rsqrtf((float)(d + 1));
    }
    if (t == 255) g_bsum[blockIdx.x] = incl;
}

// merged: every block redundantly scans the 196 block sums, then fixes up its slice
__global__ void k_fixup() {
    __shared__ int sm[256];
    int t = threadIdx.x;
    sm[t] = (t < NB_SCAN) ? g_bsum[t] : 0;
    __syncthreads();
    for (int off = 1; off < 256; off <<= 1) {
        int u = (t >= off) ? sm[t - off] : 0;
        __syncthreads();
        sm[t] += u;
        __syncthreads();
    }
    int boff = (blockIdx.x > 0) ? sm[blockIdx.x - 1] : 0;
    int i = blockIdx.x * 256 + t;
    if (i < N_NODES)
        g_rowptr[i] = g_rowptr[i] + boff;
    if (i == 0) g_rowptr[N_NODES] = N_EDGES;
}

// atomic-free scatter: slot = rowptr[dst] + saved sequence number
__global__ void k_scatter(const int* __restrict__ ei) {
    int t = blockIdx.x * blockDim.x + threadIdx.x;
    int e = t * 4;
    if (e < N_EDGES) {
        int4 s = *(const int4*)&ei[e];
        int4 d = *(const int4*)&ei[N_EDGES + e];
        int4 p = *(const int4*)&g_epos[e];
        g_csrsrc[g_rowptr[d.x] + p.x] = s.x;
        g_csrsrc[g_rowptr[d.y] + p.y] = s.y;
        g_csrsrc[g_rowptr[d.z] + p.z] = s.z;
        g_csrsrc[g_rowptr[d.w] + p.w] = s.w;
    }
}

// ---------------- tensor-core GEMM (HMMA bf16, fp32 accum) ----------------------
#define APAD 40   // bf16 per A smem row (32 used)
#define BPAD 72   // bf16 per B smem row (64 used)

__device__ __forceinline__ void ldsm_x4(unsigned* r, unsigned addr) {
    asm volatile("ldmatrix.sync.aligned.m8n8.x4.shared.b16 {%0,%1,%2,%3}, [%4];"
                 : "=r"(r[0]), "=r"(r[1]), "=r"(r[2]), "=r"(r[3]) : "r"(addr));
}
__device__ __forceinline__ void ldsm_x4_t(unsigned* r, unsigned addr) {
    asm volatile("ldmatrix.sync.aligned.m8n8.x4.trans.shared.b16 {%0,%1,%2,%3}, [%4];"
                 : "=r"(r[0]), "=r"(r[1]), "=r"(r[2]), "=r"(r[3]) : "r"(addr));
}
__device__ __forceinline__ void mma_bf16(float* c, const unsigned* a,
                                         unsigned b0, unsigned b1) {
    asm volatile(
        "mma.sync.aligned.m16n8k16.row.col.f32.bf16.bf16.f32 "
        "{%0,%1,%2,%3}, {%4,%5,%6,%7}, {%8,%9}, {%0,%1,%2,%3};"
        : "+f"(c[0]), "+f"(c[1]), "+f"(c[2]), "+f"(c[3])
        : "r"(a[0]), "r"(a[1]), "r"(a[2]), "r"(a[3]), "r"(b0), "r"(b1));
}

__global__ __launch_bounds__(256) void k_gemm(const float* __restrict__ Aext,
                                              const float* __restrict__ W,
                                              int K, int nCols, int mode) {
    const float* __restrict__ A = (mode == 0) ? Aext : g_h;

    __shared__ __nv_bfloat16 As[128 * APAD];
    __shared__ __nv_bfloat16 Bs[32 * BPAD];

    int tid  = threadIdx.x;
    int lane = tid & 31, warp = tid >> 5;
    int wr = warp >> 1, wc = warp & 1;         // 4 x 2 warp grid
    int m0 = blockIdx.x * 128;
    int colb = blockIdx.y * 64;

    unsigned As_base = (unsigned)__cvta_generic_to_shared(As);
    unsigned Bs_base = (unsigned)__cvta_generic_to_shared(Bs);

    float c[2][4][4] = {};

    for (int k0 = 0; k0 < K; k0 += 32) {
#pragma unroll
        for (int i = 0; i < 4; i++) {
            int li  = i * 256 + tid;
            int row = li >> 3, seg = li & 7;
            float4 av = make_float4(0.f, 0.f, 0.f, 0.f);
            int grow = m0 + row;
            if (grow < N_NODES)
                av = *(const float4*)&A[(long)grow * K + k0 + seg * 4];
            __nv_bfloat162 p0 = __floats2bfloat162_rn(av.x, av.y);
            __nv_bfloat162 p1 = __floats2bfloat162_rn(av.z, av.w);
            *(__nv_bfloat162*)&As[row * APAD + seg * 4]     = p0;
            *(__nv_bfloat162*)&As[row * APAD + seg * 4 + 2] = p1;
        }
#pragma unroll
        for (int i = 0; i < 2; i++) {
            int li  = i * 256 + tid;
            int row = li >> 4, seg = li & 15;
            float4 wv = *(const float4*)&W[(long)(k0 + row) * nCols + colb + seg * 4];
            __nv_bfloat162 p0 = __floats2bfloat162_rn(wv.x, wv.y);
            __nv_bfloat162 p1 = __floats2bfloat162_rn(wv.z, wv.w);
            *(__nv_bfloat162*)&Bs[row * BPAD + seg * 4]     = p0;
            *(__nv_bfloat162*)&Bs[row * BPAD + seg * 4 + 2] = p1;
        }
        __syncthreads();

#pragma unroll
        for (int kk = 0; kk < 2; kk++) {
            int k16 = kk * 16;
            unsigned a[2][4], b[2][4];
            int arow = wr * 32 + (lane & 15);
            int acol = k16 + (lane >> 4) * 8;
#pragma unroll
            for (int mi = 0; mi < 2; mi++)
                ldsm_x4(a[mi], As_base + ((arow + mi * 16) * APAD + acol) * 2);
            int brow = k16 + (lane & 15);
#pragma unroll
            for (int ni = 0; ni < 2; ni++) {
                int bcol = wc * 32 + ni * 16 + (lane >> 4) * 8;
                ldsm_x4_t(b[ni], Bs_base + (brow * BPAD + bcol) * 2);
            }
#pragma unroll
            for (int mi = 0; mi < 2; mi++)
#pragma unroll
                for (int j = 0; j < 4; j++)
                    mma_bf16(c[mi][j], a[mi], b[j >> 1][(j & 1) * 2],
                             b[j >> 1][(j & 1) * 2 + 1]);
        }
        __syncthreads();
    }

    __nv_bfloat162* outp = (mode == 2) ? g_hh2 : g_t2;
    int ostride = (mode == 2) ? 128 : 32;
    int obase   = (mode == 2) ? (colb >> 1) : 0;
    int trow = lane >> 2, tq = lane & 3;
#pragma unroll
    for (int mi = 0; mi < 2; mi++) {
#pragma unroll
        for (int j = 0; j < 4; j++) {
            int row  = m0 + wr * 32 + mi * 16 + trow;
            int cidx = obase + wc * 16 + j * 4 + tq;
            if (row < N_NODES)
                outp[row * ostride + cidx] = __floats2bfloat162_rn(c[mi][j][0], c[mi][j][1]);
            if (row + 8 < N_NODES)
                outp[(row + 8) * ostride + cidx] = __floats2bfloat162_rn(c[mi][j][2], c[mi][j][3]);
        }
    }
}

// ---------------- GCN layer 1 (serial shfl-broadcast form) ----------------
__global__ void k_gcn(const float* __restrict__ bias) {
    int warp = (blockIdx.x * blockDim.x + threadIdx.x) >> 5;
    int lane = threadIdx.x & 31;
    if (warp >= N_NODES) return;
    int dst = warp;
    int r0 = g_rowptr[dst], r1 = g_rowptr[dst + 1];
    float wd = g_dinv[dst];
    const __nv_bfloat162* __restrict__ t2 = g_t2;
    float2 f = __bfloat1622float2(t2[dst * 32 + lane]);   // self-loop
    float acc0 = f.x * wd;
    float acc1 = f.y * wd;
    for (int e0 = r0; e0 < r1; e0 += 32) {
        int idx = e0 + lane;
        int s = 0; float w = 0.f;
        if (idx < r1) { s = g_csrsrc[idx]; w = g_dinv[s]; }
        int cnt = min(32, r1 - e0);
        for (int j = 0; j < cnt; j++) {
            int   ss = __shfl_sync(0xffffffffu, s, j);
            float ww = __shfl_sync(0xffffffffu, w, j);
            float2 v = __bfloat1622float2(t2[ss * 32 + lane]);
            acc0 += v.x * ww;
            acc1 += v.y * ww;
        }
    }
    float2 b = *(const float2*)&bias[2 * lane];
    float2 o;
    o.x = fmaxf(acc0 * wd + b.x, 0.f);
    o.y = fmaxf(acc1 * wd + b.y, 0.f);
    *(float2*)&g_h[dst * 64 + 2 * lane] = o;
}

// ---------------- GCN layer 2 + fused attention logits ----------------
__global__ void k_gcn2att(const float* __restrict__ bias) {
    int warp = (blockIdx.x * blockDim.x + threadIdx.x) >> 5;
    int lane = threadIdx.x & 31;
    if (warp >= N_NODES) return;
    int dst = warp;
    int r0 = g_rowptr[dst], r1 = g_rowptr[dst + 1];
    float wd = g_dinv[dst];
    const __nv_bfloat162* __restrict__ t2 = g_t2;
    float2 f = __bfloat1622float2(t2[dst * 32 + lane]);   // self-loop
    float acc0 = f.x * wd;
    float acc1 = f.y * wd;
    for (int e0 = r0; e0 < r1; e0 += 32) {
        int idx = e0 + lane;
        int s = 0; float w = 0.f;
        if (idx < r1) { s = g_csrsrc[idx]; w = g_dinv[s]; }
        int cnt = min(32, r1 - e0);
        for (int j = 0; j < cnt; j++) {
            int   ss = __shfl_sync(0xffffffffu, s, j);
            float ww = __shfl_sync(0xffffffffu, w, j);
            float2 v = __bfloat1622float2(t2[ss * 32 + lane]);
            acc0 += v.x * ww;
            acc1 += v.y * ww;
        }
    }
    float2 b = *(const float2*)&bias[2 * lane];
    float hx = fmaxf(acc0 * wd + b.x, 0.f);
    float hy = fmaxf(acc1 * wd + b.y, 0.f);
    *(float2*)&g_h[dst * 64 + 2 * lane] = make_float2(hx, hy);

    // fused attention logits: ps[h] = sum_k h[k]*Ms[k,h] (lane owns k=2l,2l+1)
    float4 ms0 = *(const float4*)&g_Ms[(2 * lane) * 4];
    float4 ms1 = *(const float4*)&g_Ms[(2 * lane + 1) * 4];
    float4 md0 = *(const float4*)&g_Md[(2 * lane) * 4];
    float4 md1 = *(const float4*)&g_Md[(2 * lane + 1) * 4];
    float ps0 = hx * ms0.x + hy * ms1.x;
    float ps1 = hx * ms0.y + hy * ms1.y;
    float ps2 = hx * ms0.z + hy * ms1.z;
    float ps3 = hx * ms0.w + hy * ms1.w;
    float pd0 = hx * md0.x + hy * md1.x;
    float pd1 = hx * md0.y + hy * md1.y;
    float pd2 = hx * md0.z + hy * md1.z;
    float pd3 = hx * md0.w + hy * md1.w;
#pragma unroll
    for (int off = 16; off > 0; off >>= 1) {
        ps0 += __shfl_xor_sync(0xffffffffu, ps0, off);
        ps1 += __shfl_xor_sync(0xffffffffu, ps1, off);
        ps2 += __shfl_xor_sync(0xffffffffu, ps2, off);
        ps3 += __shfl_xor_sync(0xffffffffu, ps3, off);
        pd0 += __shfl_xor_sync(0xffffffffu, pd0, off);
        pd1 += __shfl_xor_sync(0xffffffffu, pd1, off);
        pd2 += __shfl_xor_sync(0xffffffffu, pd2, off);
        pd3 += __shfl_xor_sync(0xffffffffu, pd3, off);
    }
    if (lane == 0) {
        ((float4*)g_as)[dst] = make_float4(ps0, ps1, ps2, ps3);
        ((float4*)g_ad)[dst] = make_float4(pd0, pd1, pd2, pd3);
    }
}

__device__ __forceinline__ float pick4(float x, float y, float z, float w, int h) {
    return h == 0 ? x : h == 1 ? y : h == 2 ? z : w;
}

// ---------------- GAT phase 1: per-edge alpha + per-dst sums (side stream) -------
// no max-subtraction: logits are O(1..10), exp is safe in fp32; /s normalizes.
__global__ void k_gat1() {
    int warp = (blockIdx.x * blockDim.x + threadIdx.x) >> 5;
    int lane = threadIdx.x & 31;
    if (warp >= N_NODES) return;
    int dst = warp;
    int r0 = g_rowptr[dst], r1 = g_rowptr[dst + 1];
    const float4* as4 = (const float4*)g_as;
    float4 adv = ((const float4*)g_ad)[dst];

    float s0 = 0.f, s1 = 0.f, s2 = 0.f, s3 = 0.f;
    for (int e = r0 + lane; e < r1; e += 32) {
        int src = g_csrsrc[e];
        float4 av = as4[src];
        float a0 = __expf(lrelu(av.x + adv.x));
        float a1 = __expf(lrelu(av.y + adv.y));
        float a2 = __expf(lrelu(av.z + adv.z));
        float a3 = __expf(lrelu(av.w + adv.w));
        s0 += a0; s1 += a1; s2 += a2; s3 += a3;
        float2 pk;
        ((__nv_bfloat162*)&pk)[0] = __floats2bfloat162_rn(a0, a1);
        ((__nv_bfloat162*)&pk)[1] = __floats2bfloat162_rn(a2, a3);
        *(float2*)&g_alf[2 * e] = pk;       // 8B coalesced-ish write
    }
    if (lane == 0) {   // self-loop contributes to the sum
        float4 av = as4[dst];
        s0 += __expf(lrelu(av.x + adv.x));
        s1 += __expf(lrelu(av.y + adv.y));
        s2 += __expf(lrelu(av.z + adv.z));
        s3 += __expf(lrelu(av.w + adv.w));
    }
#pragma unroll
    for (int off = 16; off > 0; off >>= 1) {
        s0 += __shfl_down_sync(0xffffffffu, s0, off);
        s1 += __shfl_down_sync(0xffffffffu, s1, off);
        s2 += __shfl_down_sync(0xffffffffu, s2, off);
        s3 += __shfl_down_sync(0xffffffffu, s3, off);
    }
    if (lane == 0)
        g_si4[dst] = make_float4(1.f / s0, 1.f / s1, 1.f / s2, 1.f / s3);
}

// ---------------- GAT phase 2: serial weighted bf16 gather, alpha from table -----
__device__ __forceinline__ void acc8(float4 raw, float al,
                                     float& a0, float& a1, float& a2, float& a3,
                                     float& a4, float& a5, float& a6, float& a7) {
    const __nv_bfloat162* bp = (const __nv_bfloat162*)&raw;
    float2 f0 = __bfloat1622float2(bp[0]);
    float2 f1 = __bfloat1622float2(bp[1]);
    float2 f2 = __bfloat1622float2(bp[2]);
    float2 f3 = __bfloat1622float2(bp[3]);
    a0 += f0.x * al; a1 += f0.y * al; a2 += f1.x * al; a3 += f1.y * al;
    a4 += f2.x * al; a5 += f2.y * al; a6 += f3.x * al; a7 += f3.y * al;
}

__global__ void k_gat2() {
    int warp = (blockIdx.x * blockDim.x + threadIdx.x) >> 5;
    int lane = threadIdx.x & 31;
    if (warp >= N_NODES) return;
    int dst = warp;
    int r0 = g_rowptr[dst], r1 = g_rowptr[dst + 1];
    float4 adv = ((const float4*)g_ad)[dst];
    float4 iv  = g_si4[dst];

    int head = lane >> 3;
    float inv = pick4(iv.x, iv.y, iv.z, iv.w, head);
    float adh = pick4(adv.x, adv.y, adv.z, adv.w, head);
    int hp = head >> 1;          // which bf16x2 word holds this head
    int hl = head & 1;           // low/high half

    const float4* hh4 = (const float4*)g_hh2;   // 32 float4 per node row
    float a0 = 0.f, a1 = 0.f, a2 = 0.f, a3 = 0.f, a4 = 0.f, a5 = 0.f, a6 = 0.f, a7 = 0.f;
    {   // self-loop (one exp per dst — cheap)
        float ash = g_as[dst * 4 + head];
        float al  = __expf(lrelu(ash + adh)) * inv;
        acc8(hh4[dst * 32 + lane], al, a0, a1, a2, a3, a4, a5, a6, a7);
    }
    for (int e0 = r0; e0 < r1; e0 += 32) {
        int idx = e0 + lane;
        int sv = (idx < r1) ? g_csrsrc[idx] : 0;
        int cnt = min(32, r1 - e0);
        int j = 0;
        for (; j + 2 <= cnt; j += 2) {          // unroll-by-2: both loads in flight
            int srcA = __shfl_sync(0xffffffffu, sv, j);
            int srcB = __shfl_sync(0xffffffffu, sv, j + 1);
            float2 awA = __bfloat1622float2(g_alf[2 * (e0 + j) + hp]);
            float2 awB = __bfloat1622float2(g_alf[2 * (e0 + j + 1) + hp]);
            float4 rA = hh4[srcA * 32 + lane];
            float4 rB = hh4[srcB * 32 + lane];
            float alA = (hl ? awA.y : awA.x) * inv;
            float alB = (hl ? awB.y : awB.x) * inv;
            acc8(rA, alA, a0, a1, a2, a3, a4, a5, a6, a7);
            acc8(rB, alB, a0, a1, a2, a3, a4, a5, a6, a7);
        }
        for (; j < cnt; j++) {
            int src = __shfl_sync(0xffffffffu, sv, j);
            float2 aw = __bfloat1622float2(g_alf[2 * (e0 + j) + hp]);
            float al  = (hl ? aw.y : aw.x) * inv;
            acc8(hh4[src * 32 + lane], al, a0, a1, a2, a3, a4, a5, a6, a7);
        }
    }
    float4 ov;
    __nv_bfloat162* op = (__nv_bfloat162*)&ov;
    op[0] = __floats2bfloat162_rn(a0, a1);
    op[1] = __floats2bfloat162_rn(a2, a3);
    op[2] = __floats2bfloat162_rn(a4, a5);
    op[3] = __floats2bfloat162_rn(a6, a7);
    *(float4*)&g_gat2[dst * 128 + lane * 4] = ov;
}

// ---------------- pooling (batch is sorted) ----------------
__global__ void k_gstart(const int* __restrict__ batch) {
    int n = blockIdx.x * blockDim.x + threadIdx.x;
    if (n >= N_NODES) return;
    int b = batch[n];
    if (n == 0)
        for (int g = 0; g <= b; g++) g_gstart[g] = 0;
    if (n == N_NODES - 1) {
        for (int g = b + 1; g <= NG; g++) g_gstart[g] = N_NODES;
    } else {
        int b2 = batch[n + 1];
        for (int g = b + 1; g <= b2; g++) g_gstart[g] = n + 1;
    }
}

// grid dim3(NG, 4): 32 bf16-pair channels x 8 node-slots per block
__global__ void k_pool(const float* __restrict__ bg) {
    int g = blockIdx.x;
    int pair = blockIdx.y * 32 + (threadIdx.x & 31);   // 0..127
    int slot = threadIdx.x >> 5;                       // 0..7
    int st = g_gstart[g], en = g_gstart[g + 1];
    float ax = 0.f, ay = 0.f;
    for (int n = st + slot; n < en; n += 8) {
        float2 v = __bfloat1622float2(g_gat2[n * 128 + pair]);
        ax += v.x; ay += v.y;
    }
    __shared__ float smx[256], smy[256];
    smx[threadIdx.x] = ax; smy[threadIdx.x] = ay;
    __syncthreads();
    if (slot == 0) {
        int pl = threadIdx.x & 31;
        float tx = 0.f, ty = 0.f;
#pragma unroll
        for (int s = 0; s < 8; s++) { tx += smx[s * 32 + pl]; ty += smy[s * 32 + pl]; }
        int cnt = en - st;
        float vx = 0.f, vy = 0.f;
        if (cnt > 0) {
            float ic = 1.f / (float)cnt;
            vx = tx * ic + bg[pair * 2];
            vy = ty * ic + bg[pair * 2 + 1];
        }
        *(float2*)&g_pool[g * 256 + pair * 2] = make_float2(vx, vy);
    }
}

// ---------------- final MLP ----------------
__global__ void k_mlp(const float* __restrict__ Wf1, const float* __restrict__ bf1,
                      const float* __restrict__ Wf2, const float* __restrict__ bf2,
                      float* __restrict__ out) {
    int g = blockIdx.x;
    int j = threadIdx.x;   // 64 threads
    float acc = bf1[j];
    const float* p = &g_pool[g * 256];
    for (int c = 0; c < 256; c++)
        acc += p[c] * Wf1[c * 64 + j];
    float z = fmaxf(acc, 0.f) * Wf2[j];
#pragma unroll
    for (int off = 16; off > 0; off >>= 1)
        z += __shfl_xor_sync(0xffffffffu, z, off);
    __shared__ float sm[2];
    if ((threadIdx.x & 31) == 0) sm[threadIdx.x >> 5] = z;
    __syncthreads();
    if (threadIdx.x == 0) out[g] = sm[0] + sm[1] + bf2[0];
}

// ---------------- launch ----------------
extern "C" void kernel_launch(void* const* d_in, const int* in_sizes, int n_in,
                              void* d_out, int out_size) {
    const float* x       = (const float*)d_in[0];
    const int*   ei      = (const int*)  d_in[1];
    const int*   batch   = (const int*)  d_in[2];
    const float* W1      = (const float*)d_in[3];
    const float* b1      = (const float*)d_in[4];
    const float* W2      = (const float*)d_in[5];
    const float* b2      = (const float*)d_in[6];
    const float* Wg      = (const float*)d_in[7];
    const float* att_src = (const float*)d_in[8];
    const float* att_dst = (const float*)d_in[9];
    const float* bg      = (const float*)d_in[10];
    const float* Wf1     = (const float*)d_in[11];
    const float* bf1     = (const float*)d_in[12];
    const float* Wf2     = (const float*)d_in[13];
    const float* bf2     = (const float*)d_in[14];
    float* out = (float*)d_out;

    // lazily created side-stream resources (first call is the non-captured
    // correctness run; creation happens there, never during capture)
    static cudaStream_t s1 = nullptr;
    static cudaEvent_t  ev_fork = nullptr, ev_csr = nullptr;
    static cudaEvent_t  ev_h = nullptr, ev_att = nullptr;
    if (!s1) {
        cudaStreamCreateWithFlags(&s1, cudaStreamNonBlocking);
        cudaEventCreateWithFlags(&ev_fork, cudaEventDisableTiming);
        cudaEventCreateWithFlags(&ev_csr,  cudaEventDisableTiming);
        cudaEventCreateWithFlags(&ev_h,    cudaEventDisableTiming);
        cudaEventCreateWithFlags(&ev_att,  cudaEventDisableTiming);
    }

    dim3 gemm_grid1((N_NODES + 127) / 128, 1);
    dim3 gemm_grid4((N_NODES + 127) / 128, 4);
    int  warp_blocks = (N_NODES + 7) / 8;   // 8 warps / 256-thread block

    // fork: CSR chain (+fold) on side stream, concurrent with GEMM1
    cudaEventRecord(ev_fork, 0);
    cudaStreamWaitEvent(s1, ev_fork, 0);

    k_hist      <<<(N_EDGES / 8 + 255) / 256, 256, 0, s1>>>(ei);
    k_scan_local<<<NB_SCAN + 1, 256, 0, s1>>>(Wg, att_src, att_dst);
    k_fixup     <<<NB_SCAN, 256, 0, s1>>>();
    k_scatter   <<<(N_EDGES / 4 + 255) / 256, 256, 0, s1>>>(ei);
    cudaEventRecord(ev_csr, s1);            // join: CSR + fold ready
    k_gstart    <<<(N_NODES + 255) / 256, 256, 0, s1>>>(batch);

    // main stream: GEMM1 overlaps the CSR build
    k_gemm<<<gemm_grid1, 256>>>(x, W1, F_INPUT, 64, 0);

    // join: aggregation needs CSR (and fold, for gcn2att)
    cudaStreamWaitEvent(0, ev_csr, 0);

    k_gcn    <<<warp_blocks, 256>>>(b1);
    k_gemm   <<<gemm_grid1, 256>>>(x, W2, 64, 64, 1);
    k_gcn2att<<<warp_blocks, 256>>>(b2);    // gcn layer2 + attention logits fused

    // fork: per-edge alpha (needs g_as/g_ad + CSR, NOT hh2), hidden under GEMM3
    cudaEventRecord(ev_h, 0);
    cudaStreamWaitEvent(s1, ev_h, 0);
    k_gat1<<<warp_blocks, 256, 0, s1>>>();
    cudaEventRecord(ev_att, s1);

    k_gemm<<<gemm_grid4, 256>>>(x, Wg, 64, 256, 2);
    cudaStreamWaitEvent(0, ev_att, 0);      // also orders gstart before pool

    k_gat2<<<warp_blocks, 256>>>();
    k_pool<<<dim3(NG, 4), 256>>>(bg);
    k_mlp <<<NG, 64>>>(Wf1, bf1, Wf2, bf2, out);
}